// round 17
// baseline (speedup 1.0000x reference)
#include <cuda_runtime.h>
#include <cuda_fp16.h>
#include <math.h>
#include <stdint.h>

// Problem constants
#define NB 8
#define NC 128
#define NHW 16384
#define NE 4
#define NR 64

// All main-kernel tiles: 128 rows x 68 words (136 halves). Word offsets:
#define LDH 68
#define RA  0        // X' acts [px][k] (gs-scaled)
#define RS  8704     // S acts [px][k]  (later reused for T)
#define RW0 17408    // W0cat  [m][k]
#define RPJ 26112    // proj   [m][k]
#define RW1 34816    // W1cat  [m][k]
#define RMC 43520    // Mcat   [d][rank]
#define SMEM_MAIN (52224 * 4)   // 208896 bytes

// ---------------- device scratch ----------------
__device__ float g_fe0[NB * NC];
__device__ float g_pooled[NB * NC];
__device__ int   g_sel[NB * 2];
__device__ float g_gate[NB * 2];
__device__ float g_gsum[NB];
// pre-converted fp16 weights (packed half2 words, +slack for cp alignment)
__device__ __align__(16) uint32_t g_w0h[NE * NR * 64 + 8];   // [e][r][64w]
__device__ __align__(16) uint32_t g_w1h[NE * NR * 64 + 8];
__device__ __align__(16) uint32_t g_pw2h[NE * NC * 32 + 8];  // [e][d][32w]
__device__ __align__(16) uint32_t g_projh[NC * 64 + 8];      // [d][64w]

__device__ __forceinline__ float gelu_f(float v) {
    return 0.5f * v * (1.0f + erff(v * 0.70710678118654752440f));
}
__device__ __forceinline__ float gelu_fast(float v) {
    float u = 0.7978845608f * (v + 0.044715f * v * v * v);
    float th;
    asm("tanh.approx.f32 %0, %1;" : "=f"(th) : "f"(u));
    return 0.5f * v * (1.0f + th);
}
__device__ __forceinline__ uint32_t pack2(float a, float b) {
    __half2 h = __floats2half2_rn(a, b);
    return *(uint32_t*)&h;
}
__device__ __forceinline__ void mma_f16(float* c, const uint32_t* a, uint32_t b0, uint32_t b1) {
    asm volatile(
        "mma.sync.aligned.m16n8k16.row.col.f32.f16.f16.f32 "
        "{%0,%1,%2,%3}, {%4,%5,%6,%7}, {%8,%9}, {%0,%1,%2,%3};"
        : "+f"(c[0]), "+f"(c[1]), "+f"(c[2]), "+f"(c[3])
        : "r"(a[0]), "r"(a[1]), "r"(a[2]), "r"(a[3]), "r"(b0), "r"(b1));
}
__device__ __forceinline__ void ldsm4(uint32_t* r, uint32_t saddr) {
    asm volatile("ldmatrix.sync.aligned.m8n8.x4.shared.b16 {%0,%1,%2,%3}, [%4];"
        : "=r"(r[0]), "=r"(r[1]), "=r"(r[2]), "=r"(r[3]) : "r"(saddr));
}
__device__ __forceinline__ void cp16(uint32_t saddr, const uint32_t* g) {
    asm volatile("{ .reg .u64 ga; cvta.to.global.u64 ga, %1; "
                 "cp.async.ca.shared.global [%0], [ga], 16; }"
                 :: "r"(saddr), "l"(g) : "memory");
}
#define CP_COMMIT() asm volatile("cp.async.commit_group;" ::: "memory")
#define CP_WAIT0()  asm volatile("cp.async.wait_group 0;" ::: "memory")

// ---------------------------------------------------------------------------
// Kernel 1 (fused): [0,512) conv stencil; [512,640) PW2 -> fp16;
//   [640,660) fp16 pack of exp_w0 / exp_w1 / proj_w.
// ---------------------------------------------------------------------------
__global__ __launch_bounds__(256) void conv_pw2_kernel(
    const float* __restrict__ x, const float* __restrict__ exp_w2,
    const float* __restrict__ proj_w, const float* __restrict__ exp_w0,
    const float* __restrict__ exp_w1) {
    const int t = threadIdx.x;
    if (blockIdx.x >= 640) {
        int c = blockIdx.x - 640;
        const float* src;
        uint32_t* dst;
        if (c < 8)       { src = exp_w0 + c * 4096;        dst = g_w0h + c * 2048; }
        else if (c < 16) { src = exp_w1 + (c - 8) * 4096;  dst = g_w1h + (c - 8) * 2048; }
        else             { src = proj_w + (c - 16) * 4096; dst = g_projh + (c - 16) * 2048; }
        #pragma unroll
        for (int i = 0; i < 4; ++i) {
            int f = t + (i << 8);
            float4 u = ((const float4*)src)[f];
            uint2 w;
            w.x = pack2(u.x, u.y);
            w.y = pack2(u.z, u.w);
            ((uint2*)dst)[f] = w;
        }
        return;
    }
    if (blockIdx.x >= 512) {
        int bi = blockIdx.x - 512;
        int e = bi >> 5;
        int d = ((bi & 31) << 2) + (t >> 6);
        int r = t & 63;
        const float* pw = proj_w + d * NC;
        const float* w2 = exp_w2 + (size_t)e * NC * NR + r;
        float a = 0.f;
        #pragma unroll 8
        for (int c = 0; c < NC; ++c) a += pw[c] * w2[c * NR];
        ((__half*)g_pw2h)[(e * NC + d) * NR + r] = __float2half_rn(a);
        return;
    }

    // ---- conv stencil: 2 planes/block, rolling registers, shfl halos ----
    const int wid = t >> 5, lane = t & 31;
    const int plane = blockIdx.x * 2 + (wid >> 2);
    const int w4 = wid & 3;
    const float* p = x + (size_t)plane * NHW + lane * 4;
    const int r0 = w4 * 32;

    const float4 z = make_float4(0.f, 0.f, 0.f, 0.f);
    float4 prev = (r0 > 0) ? *(const float4*)(p + (r0 - 1) * 128) : z;
    float4 cur  = *(const float4*)(p + r0 * 128);
    float4 nxt  = *(const float4*)(p + (r0 + 1) * 128);
    float4 nxt2 = *(const float4*)(p + (r0 + 2) * 128);

    float sumg = 0.f, sumx = 0.f;
    #pragma unroll 4
    for (int i = 0; i < 32; ++i) {
        int rn = r0 + i + 3;
        float4 inc = (rn < 128) ? *(const float4*)(p + rn * 128) : z;

        sumx += cur.x + cur.y + cur.z + cur.w;

        float pl = __shfl_up_sync(0xffffffffu, prev.w, 1);
        float cl = __shfl_up_sync(0xffffffffu, cur.w, 1);
        float nl = __shfl_up_sync(0xffffffffu, nxt.w, 1);
        float pr = __shfl_down_sync(0xffffffffu, prev.x, 1);
        float cr = __shfl_down_sync(0xffffffffu, cur.x, 1);
        float nr = __shfl_down_sync(0xffffffffu, nxt.x, 1);
        if (lane == 0)  { pl = 0.f; cl = 0.f; nl = 0.f; }
        if (lane == 31) { pr = 0.f; cr = 0.f; nr = 0.f; }

        float nb0 = pl + prev.x + prev.y + cl + cur.y + nl + nxt.x + nxt.y;
        float nb1 = prev.x + prev.y + prev.z + cur.x + cur.z + nxt.x + nxt.y + nxt.z;
        float nb2 = prev.y + prev.z + prev.w + cur.y + cur.w + nxt.y + nxt.z + nxt.w;
        float nb3 = prev.z + prev.w + pr + cur.z + cr + nxt.z + nxt.w + nr;

        sumg += gelu_fast(8.f * cur.x - nb0);
        sumg += gelu_fast(8.f * cur.y - nb1);
        sumg += gelu_fast(8.f * cur.z - nb2);
        sumg += gelu_fast(8.f * cur.w - nb3);

        prev = cur; cur = nxt; nxt = nxt2; nxt2 = inc;
    }

    for (int o = 16; o > 0; o >>= 1) {
        sumg += __shfl_down_sync(0xffffffffu, sumg, o);
        sumx += __shfl_down_sync(0xffffffffu, sumx, o);
    }
    __shared__ float rg[8], rx[8];
    if (lane == 0) { rg[wid] = sumg; rx[wid] = sumx; }
    __syncthreads();
    if (t < 2) {
        float ag = 0.f, ax = 0.f;
        #pragma unroll
        for (int i = 0; i < 4; ++i) { ag += rg[t * 4 + i]; ax += rx[t * 4 + i]; }
        const float inv = 1.0f / 16384.0f;
        int pl = blockIdx.x * 2 + t;
        g_fe0[pl]    = ag * inv;
        g_pooled[pl] = ax * inv;
    }
}

// ---------------------------------------------------------------------------
// Kernel 2: routing, one block per batch
// ---------------------------------------------------------------------------
__global__ __launch_bounds__(256) void routing_kernel(
    const float* __restrict__ mlp_w1, const float* __restrict__ mlp_b1,
    const float* __restrict__ mlp_w2, const float* __restrict__ mlp_b2,
    const float* __restrict__ gate_w, const float* __restrict__ fgate_w) {
    __shared__ float s_in[NC], s_pool[NC], s_h1[256], s_fe[NC], s_log[NE];
    const int b = blockIdx.x;
    const int t = threadIdx.x;

    if (t < NC) { s_in[t] = g_fe0[b * NC + t]; s_pool[t] = g_pooled[b * NC + t]; }
    __syncthreads();
    {
        float a = mlp_b1[t];
        #pragma unroll 8
        for (int c = 0; c < NC; ++c) a += s_in[c] * mlp_w1[c * 256 + t];
        s_h1[t] = gelu_f(a);
    }
    __syncthreads();
    if (t < NC) {
        float a = mlp_b2[t];
        #pragma unroll 8
        for (int c = 0; c < 256; ++c) a += s_h1[c] * mlp_w2[c * NC + t];
        s_fe[t] = a;
    }
    __syncthreads();
    if (t < NE) {
        float a = 0.f;
        for (int c = 0; c < NC; ++c)
            a += s_pool[c] * gate_w[c * NE + t] + s_fe[c] * fgate_w[c * NE + t];
        s_log[t] = a;
    }
    __syncthreads();
    if (t == 0) {
        float sc[NE];
        float m = -1e30f;
        #pragma unroll
        for (int e = 0; e < NE; ++e) { sc[e] = s_log[e]; m = fmaxf(m, sc[e]); }
        float ss = 0.f;
        #pragma unroll
        for (int e = 0; e < NE; ++e) { sc[e] = expf(sc[e] - m); ss += sc[e]; }
        float inv = 1.0f / ss;
        #pragma unroll
        for (int e = 0; e < NE; ++e) sc[e] *= inv;
        int i0 = 0;
        #pragma unroll
        for (int e = 1; e < NE; ++e) if (sc[e] > sc[i0]) i0 = e;
        int i1 = -1;
        #pragma unroll
        for (int e = 0; e < NE; ++e) {
            if (e == i0) continue;
            if (i1 < 0 || sc[e] > sc[i1]) i1 = e;
        }
        g_sel[b * 2] = i0;  g_sel[b * 2 + 1] = i1;
        g_gate[b * 2] = sc[i0]; g_gate[b * 2 + 1] = sc[i1];
        g_gsum[b] = sc[i0] + sc[i1];
    }
}

// ---------------------------------------------------------------------------
// Main fp16 tensor-core kernel: 1024 threads, 32 warps (8M x 4N of 16x32),
// ldmatrix for BOTH operands, K=256 fused final GEMM (X' = gs*X).
// ---------------------------------------------------------------------------

// stage activations [128 c][128 px] f32 -> [px][k packed half2], scaled
__device__ __forceinline__ void stage_act_h(uint32_t* smw, const float* __restrict__ gsrc,
                                            float sc, int t) {
    #pragma unroll
    for (int i = 0; i < 4; ++i) {
        int unit = t + (i << 10);
        int px = unit & 127;
        int cq = unit >> 7;                        // 0..31, c = 4cq..4cq+3
        const float* g = gsrc + (size_t)(4 * cq) * NHW + px;
        float v0 = g[0] * sc;
        float v1 = g[NHW] * sc;
        float v2 = g[2 * NHW] * sc;
        float v3 = g[3 * NHW] * sc;
        uint2 w;
        w.x = pack2(v0, v1);
        w.y = pack2(v2, v3);
        *(uint2*)(smw + px * LDH + 2 * cq) = w;
    }
}

// one M=16/N=32 GEMM pass: acc += W[m][k] * B[k][n]  (fp16, K=128)
// A via 1 ldsm.x4 / ks ; B via 2 ldsm.x4 / ks (4 n-frags).
__device__ __forceinline__ void gemm_1(uint32_t smb, int aoff, int boff,
                                       float acc[4][4], int m0, int n0, int lane) {
    const int mat = lane >> 3, r8 = lane & 7;
    const uint32_t ab = smb + (uint32_t)((aoff + (m0 + (mat & 1) * 8 + r8) * LDH) * 4)
                            + (uint32_t)((mat >> 1) * 16);
    const uint32_t bb = smb + (uint32_t)((boff + (n0 + (mat >> 1) * 8 + r8) * LDH) * 4)
                            + (uint32_t)((mat & 1) * 16);
    #pragma unroll
    for (int ks = 0; ks < 8; ++ks) {
        const uint32_t kB = (uint32_t)ks * 32u;
        uint32_t a[4], b0[4], b1[4];
        ldsm4(a, ab + kB);
        ldsm4(b0, bb + kB);
        ldsm4(b1, bb + 16u * LDH * 4u + kB);
        mma_f16(acc[0], a, b0[0], b0[1]);
        mma_f16(acc[1], a, b0[2], b0[3]);
        mma_f16(acc[2], a, b1[0], b1[1]);
        mma_f16(acc[3], a, b1[2], b1[3]);
    }
}

#define ZERO_ACC(A) \
    { _Pragma("unroll") for (int j = 0; j < 4; ++j) \
      _Pragma("unroll") for (int kq = 0; kq < 4; ++kq) (A)[j][kq] = 0.f; }

__global__ __launch_bounds__(1024, 1) void main_mma_kernel(
    const float* __restrict__ x, const float* __restrict__ sh,
    float* __restrict__ out) {
    extern __shared__ uint32_t smem[];
    const int t = threadIdx.x;
    const int lane = t & 31;
    const int wid = t >> 5;
    const int m0 = (wid >> 2) << 4;          // 0..112 step 16
    const int n0 = (wid & 3) << 5;           // 0,32,64,96
    const int b = blockIdx.y;
    const int hw0 = blockIdx.x * 128;

    const int   e0  = g_sel[b * 2],  e1  = g_sel[b * 2 + 1];
    const float ga0 = g_gate[b * 2], ga1 = g_gate[b * 2 + 1];
    const float gs  = g_gsum[b];
    const float igs = 1.0f / gs;

    const uint32_t smb = (uint32_t)__cvta_generic_to_shared(smem);
    const uint32_t* w0a = g_w0h + (size_t)e0 * NR * 64;
    const uint32_t* w0b = g_w0h + (size_t)e1 * NR * 64;
    const uint32_t* w1a = g_w1h + (size_t)e0 * NR * 64;
    const uint32_t* w1b = g_w1h + (size_t)e1 * NR * 64;
    const uint32_t* mc0 = g_pw2h + (size_t)e0 * NC * 32;
    const uint32_t* mc1 = g_pw2h + (size_t)e1 * NC * 32;

    const float* xb = x  + (size_t)b * NC * NHW + hw0;
    const float* sb = sh + (size_t)b * NC * NHW + hw0;

    // ---- prologue: queue all 4 weight tiles, stage X' (gs-scaled) + S ----
    #pragma unroll
    for (int i = 0; i < 2; ++i) {        // W0cat
        int cid = t + (i << 10);
        int r = cid >> 4, j = (cid & 15) << 2;
        const uint32_t* src = ((r < 64) ? w0a + r * 64 : w0b + (r - 64) * 64) + j;
        cp16(smb + (uint32_t)(RW0 + r * LDH + j) * 4u, src);
    }
    #pragma unroll
    for (int i = 0; i < 2; ++i) {        // proj
        int cid = t + (i << 10);
        int r = cid >> 4, j = (cid & 15) << 2;
        cp16(smb + (uint32_t)(RPJ + r * LDH + j) * 4u, g_projh + r * 64 + j);
    }
    #pragma unroll
    for (int i = 0; i < 2; ++i) {        // W1cat
        int cid = t + (i << 10);
        int r = cid >> 4, j = (cid & 15) << 2;
        const uint32_t* src = ((r < 64) ? w1a + r * 64 : w1b + (r - 64) * 64) + j;
        cp16(smb + (uint32_t)(RW1 + r * LDH + j) * 4u, src);
    }
    #pragma unroll
    for (int i = 0; i < 2; ++i) {        // Mcat
        int cid = t + (i << 10);
        int r = cid >> 4, j = (cid & 15) << 2;
        const uint32_t* src = (j < 32) ? (mc0 + r * 32 + j) : (mc1 + r * 32 + (j - 32));
        cp16(smb + (uint32_t)(RMC + r * LDH + j) * 4u, src);
    }
    CP_COMMIT();
    stage_act_h(smem + RA, xb, gs, t);
    stage_act_h(smem + RS, sb, 1.0f, t);
    CP_WAIT0();
    __syncthreads();

    float accA[4][4]; ZERO_ACC(accA);
    float accG[4][4]; ZERO_ACC(accG);

    // GEMM1: accA = W0cat @ X'   ;   GEMM2: accG = W1cat @ S
    gemm_1(smb, RW0, RA, accA, m0, n0, lane);
    gemm_1(smb, RW1, RS, accG, m0, n0, lane);
    __syncthreads();                     // all warps done reading S (RS)

    // T = ga(row)/gs * accA * silu(accG) -> RS as [px][rank halves]
    {
        const int ar = lane >> 2, ac = lane & 3;
        __half* th = (__half*)(smem + RS);
        const float ga = ((m0 < 64) ? ga0 : ga1) * igs;
        #pragma unroll
        for (int nf = 0; nf < 4; ++nf) {
            const int col = n0 + nf * 8 + 2 * ac;
            #pragma unroll
            for (int half = 0; half < 2; ++half) {
                const int row = m0 + ar + half * 8;
                float a0 = accA[nf][half * 2 + 0];
                float a1 = accA[nf][half * 2 + 1];
                float g0 = accG[nf][half * 2 + 0];
                float g1 = accG[nf][half * 2 + 1];
                th[col * 136 + row]       = __float2half_rn(ga * a0 * (g0 / (1.f + __expf(-g0))));
                th[(col + 1) * 136 + row] = __float2half_rn(ga * a1 * (g1 / (1.f + __expf(-g1))));
            }
        }
    }
    ZERO_ACC(accA);                      // reuse as accO
    __syncthreads();

    // GEMM3 (K=256, single accumulator): accO = Mcat @ T + proj @ X'
    gemm_1(smb, RMC, RS, accA, m0, n0, lane);
    gemm_1(smb, RPJ, RA, accA, m0, n0, lane);

    // epilogue: out = accO
    {
        const int ar = lane >> 2, ac = lane & 3;
        float* ob = out + (size_t)b * NC * NHW + hw0;
        #pragma unroll
        for (int nf = 0; nf < 4; ++nf) {
            const int col = n0 + nf * 8 + 2 * ac;
            #pragma unroll
            for (int half = 0; half < 2; ++half) {
                const int row = m0 + ar + half * 8;
                float2 v = make_float2(accA[nf][half * 2 + 0],
                                       accA[nf][half * 2 + 1]);
                *(float2*)(ob + (size_t)row * NHW + col) = v;
            }
        }
    }
}

// ---------------------------------------------------------------------------
extern "C" void kernel_launch(void* const* d_in, const int* in_sizes, int n_in,
                              void* d_out, int out_size) {
    const float* x       = (const float*)d_in[0];
    const float* sh      = (const float*)d_in[1];
    const float* mlp_w1  = (const float*)d_in[2];
    const float* mlp_b1  = (const float*)d_in[3];
    const float* mlp_w2  = (const float*)d_in[4];
    const float* mlp_b2  = (const float*)d_in[5];
    const float* gate_w  = (const float*)d_in[6];
    const float* fgate_w = (const float*)d_in[7];
    const float* exp_w0  = (const float*)d_in[8];
    const float* exp_w1  = (const float*)d_in[9];
    const float* exp_w2  = (const float*)d_in[10];
    const float* proj_w  = (const float*)d_in[11];
    float* out = (float*)d_out;

    cudaFuncSetAttribute(main_mma_kernel, cudaFuncAttributeMaxDynamicSharedMemorySize, SMEM_MAIN);

    conv_pw2_kernel<<<660, 256>>>(x, exp_w2, proj_w, exp_w0, exp_w1);
    routing_kernel<<<NB, 256>>>(mlp_w1, mlp_b1, mlp_w2, mlp_b2, gate_w, fgate_w);
    main_mma_kernel<<<dim3(NHW / 128, NB), 1024, SMEM_MAIN>>>(x, sh, out);
}